// round 1
// baseline (speedup 1.0000x reference)
#include <cuda_runtime.h>
#include <cstdint>

#define BB 4
#define HH 1024
#define WW 1920
#define HW (HH * WW)
#define NPIX (BB * HW)
#define ALPHA 100.0f
#define EPSN 1e-7f

// Interleaved accumulator: [pix][4] = {num_r, num_g, num_b, den}, 16B aligned.
__device__ __align__(16) float g_acc[(size_t)NPIX * 4];

__device__ __forceinline__ void red_add_v4(float* addr, float a, float b, float c, float d) {
    asm volatile("red.global.add.v4.f32 [%0], {%1, %2, %3, %4};"
                 :: "l"(addr), "f"(a), "f"(b), "f"(c), "f"(d) : "memory");
}

__global__ __launch_bounds__(256)
void splat_kernel(const float* __restrict__ rgb1,
                  const float* __restrict__ rgb2,
                  const float* __restrict__ ftgt,
                  const float* __restrict__ f12,
                  float* __restrict__ out) {
    int idx = blockIdx.x * blockDim.x + threadIdx.x;
    if (idx >= NPIX) return;
    int b   = idx / HW;
    int rem = idx - b * HW;
    int y   = rem / WW;
    int x   = rem - y * WW;

    // ---- backwarp src2 with flow_src1_to_src2 (bilinear gather, zero outside) ----
    const float* fl = f12 + (size_t)b * 2 * HW + rem;
    float px = (float)x + fl[0];
    float py = (float)y + fl[HW];
    float x0f = floorf(px), y0f = floorf(py);
    int   x0  = (int)x0f,   y0  = (int)y0f;
    float wx = px - x0f, wy = py - y0f;

    const float* r2 = rgb2 + (size_t)b * 3 * HW;
    float a0 = 0.f, a1 = 0.f, a2 = 0.f;
#pragma unroll
    for (int cy = 0; cy < 2; cy++) {
#pragma unroll
        for (int cx = 0; cx < 2; cx++) {
            int xi = x0 + cx, yi = y0 + cy;
            if (xi >= 0 && xi < WW && yi >= 0 && yi < HH) {
                float w = (cx ? wx : 1.f - wx) * (cy ? wy : 1.f - wy);
                int o = yi * WW + xi;
                a0 += w * __ldg(r2 + o);
                a1 += w * __ldg(r2 + o + HW);
                a2 += w * __ldg(r2 + o + 2 * HW);
            }
        }
    }

    const float* r1 = rgb1 + (size_t)b * 3 * HW + rem;
    float c0 = r1[0], c1 = r1[HW], c2 = r1[2 * HW];

    float metric = (fabsf(c0 - a0) + fabsf(c1 - a1) + fabsf(c2 - a2)) * (1.f / 3.f);
    // metric section of output: after the 3-channel splat image
    out[(size_t)BB * 3 * HW + idx] = metric;

    float m  = fmaxf(-ALPHA * metric, -ALPHA);  // upper clip at +ALPHA can't trigger (metric>=0)
    float em = expf(m);

    // ---- forward splat with flow_src1_to_tgt (bilinear scatter-add) ----
    const float* ft = ftgt + (size_t)b * 2 * HW + rem;
    px = (float)x + ft[0];
    py = (float)y + ft[HW];
    x0f = floorf(px); y0f = floorf(py);
    x0 = (int)x0f; y0 = (int)y0f;
    wx = px - x0f; wy = py - y0f;

    float v0 = c0 * em, v1 = c1 * em, v2 = c2 * em;
    float* accb = g_acc + (size_t)b * HW * 4;
#pragma unroll
    for (int cy = 0; cy < 2; cy++) {
#pragma unroll
        for (int cx = 0; cx < 2; cx++) {
            int xi = x0 + cx, yi = y0 + cy;
            if (xi >= 0 && xi < WW && yi >= 0 && yi < HH) {
                float w = (cx ? wx : 1.f - wx) * (cy ? wy : 1.f - wy);
                float* p = accb + (size_t)(yi * WW + xi) * 4;
                red_add_v4(p, v0 * w, v1 * w, v2 * w, em * w);
            }
        }
    }
}

__global__ __launch_bounds__(256)
void norm_kernel(float* __restrict__ out) {
    int idx = blockIdx.x * blockDim.x + threadIdx.x;
    if (idx >= NPIX) return;
    int b   = idx / HW;
    int rem = idx - b * HW;
    float4 acc = *reinterpret_cast<const float4*>(g_acc + (size_t)idx * 4);
    float inv = 1.0f / (acc.w + EPSN);
    float* o = out + (size_t)b * 3 * HW + rem;
    o[0]      = acc.x * inv;
    o[HW]     = acc.y * inv;
    o[2 * HW] = acc.z * inv;
}

extern "C" void kernel_launch(void* const* d_in, const int* in_sizes, int n_in,
                              void* d_out, int out_size) {
    const float* rgb1 = (const float*)d_in[0];
    const float* rgb2 = (const float*)d_in[1];
    const float* ftgt = (const float*)d_in[2];  // flow_src1_to_tgt
    const float* f12  = (const float*)d_in[3];  // flow_src1_to_src2
    float* out = (float*)d_out;

    void* accp = nullptr;
    cudaGetSymbolAddress(&accp, g_acc);
    cudaMemsetAsync(accp, 0, (size_t)NPIX * 4 * sizeof(float));

    int threads = 256;
    int blocks  = (NPIX + threads - 1) / threads;
    splat_kernel<<<blocks, threads>>>(rgb1, rgb2, ftgt, f12, out);
    norm_kernel<<<blocks, threads>>>(out);
}